// round 4
// baseline (speedup 1.0000x reference)
#include <cuda_runtime.h>
#include <cuda_bf16.h>

// Problem constants
#define B_   16
#define C_   64
#define H_   256
#define W_   256
#define HW_  (H_ * W_)            // 65536
#define BHW_ (B_ * HW_)           // 1048576
#define K_   11
#define P_   5
#define EPS_ 1e-6f

// Scratch: 3 maps (sxx, sxy, syy) before and after horizontal blur.
// 12 MiB each — __device__ globals (no allocation allowed in kernel_launch).
__device__ float d_S[3 * BHW_];
__device__ float d_T[3 * BHW_];

// ---------------------------------------------------------------------------
// Kernel 1: channel reduction. Each thread owns 4 consecutive w-pixels (float4),
// loops over C=64 channels with stride HW. Fully coalesced; unrolled for MLP.
// Reads 512 MiB — this kernel is the HBM roofline term.
// ---------------------------------------------------------------------------
__global__ void k_reduce(const float4* __restrict__ x, const float4* __restrict__ y) {
    int idx = blockIdx.x * blockDim.x + threadIdx.x;   // 0 .. B*HW/4-1 = 262143
    int b = idx >> 14;                                  // HW/4 = 16384
    int p = idx & 16383;

    const float4* xp = x + (size_t)b * (C_ * (HW_ / 4)) + p;
    const float4* yp = y + (size_t)b * (C_ * (HW_ / 4)) + p;

    float4 axx = make_float4(0.f, 0.f, 0.f, 0.f);
    float4 axy = make_float4(0.f, 0.f, 0.f, 0.f);
    float4 ayy = make_float4(0.f, 0.f, 0.f, 0.f);

#pragma unroll 8
    for (int c = 0; c < C_; c++) {
        float4 xv = xp[c * (HW_ / 4)];
        float4 yv = yp[c * (HW_ / 4)];
        axx.x += xv.x * xv.x; axx.y += xv.y * xv.y; axx.z += xv.z * xv.z; axx.w += xv.w * xv.w;
        axy.x += xv.x * yv.x; axy.y += xv.y * yv.y; axy.z += xv.z * yv.z; axy.w += xv.w * yv.w;
        ayy.x += yv.x * yv.x; ayy.y += yv.y * yv.y; ayy.z += yv.z * yv.z; ayy.w += yv.w * yv.w;
    }

    float4* S4 = reinterpret_cast<float4*>(d_S);
    int out4 = b * (HW_ / 4) + p;
    S4[out4]                   = axx;
    S4[out4 + BHW_ / 4]        = axy;
    S4[out4 + 2 * (BHW_ / 4)]  = ayy;
}

// ---------------------------------------------------------------------------
// Kernel 2: horizontal 11-tap blur along w (zero padding), all 3 maps at once
// (map index folded into the linear index). Data is L2-resident (12 MiB).
// 1D factor recovered from the separable 2D gaussian:
//   g1[i] = gauss[5][i] * rsqrt(gauss[5][5])   (exact since g = g1 (x) g1)
// ---------------------------------------------------------------------------
__global__ void k_hblur(const float* __restrict__ gauss) {
    __shared__ float g1[K_];
    if (threadIdx.x < K_)
        g1[threadIdx.x] = gauss[5 * K_ + threadIdx.x] * rsqrtf(gauss[5 * K_ + 5]);
    __syncthreads();

    int idx = blockIdx.x * blockDim.x + threadIdx.x;   // 0 .. 3*BHW-1
    if (idx >= 3 * BHW_) return;
    int w       = idx & (W_ - 1);
    int rowbase = idx & ~(W_ - 1);

    float acc = 0.f;
#pragma unroll
    for (int k = 0; k < K_; k++) {
        int ww = w + k - P_;
        if ((unsigned)ww < (unsigned)W_)
            acc += g1[k] * d_S[rowbase + ww];
    }
    d_T[idx] = acc;
}

// ---------------------------------------------------------------------------
// Kernel 3: vertical 11-tap blur along h (zero padding) for all 3 maps,
// fused with the cosine-similarity combine. Stride-W loads are coalesced
// across threads (adjacent threads -> adjacent w).
// ---------------------------------------------------------------------------
__global__ void k_vblur(const float* __restrict__ gauss, float* __restrict__ out) {
    __shared__ float g1[K_];
    if (threadIdx.x < K_)
        g1[threadIdx.x] = gauss[5 * K_ + threadIdx.x] * rsqrtf(gauss[5 * K_ + 5]);
    __syncthreads();

    int idx = blockIdx.x * blockDim.x + threadIdx.x;   // 0 .. BHW-1
    if (idx >= BHW_) return;
    int w = idx & (W_ - 1);
    int h = (idx >> 8) & (H_ - 1);
    int b = idx >> 16;

    int base = b * HW_ + w;
    float sxx = 0.f, sxy = 0.f, syy = 0.f;
#pragma unroll
    for (int k = 0; k < K_; k++) {
        int hh = h + k - P_;
        if ((unsigned)hh < (unsigned)H_) {
            float g   = g1[k];
            int  off  = base + hh * W_;
            sxx += g * d_T[off];
            sxy += g * d_T[off + BHW_];
            syy += g * d_T[off + 2 * BHW_];
        }
    }
    out[idx] = sxy / (sqrtf(sxx) * sqrtf(syy) + EPS_);
}

// ---------------------------------------------------------------------------
extern "C" void kernel_launch(void* const* d_in, const int* in_sizes, int n_in,
                              void* d_out, int out_size) {
    const float4* x     = (const float4*)d_in[0];
    const float4* y     = (const float4*)d_in[1];
    const float*  gauss = (const float*)d_in[2];
    float*        out   = (float*)d_out;

    k_reduce<<<(B_ * HW_ / 4 + 255) / 256, 256>>>(x, y);
    k_hblur<<<(3 * BHW_ + 255) / 256, 256>>>(gauss);
    k_vblur<<<(BHW_ + 255) / 256, 256>>>(gauss, out);
}

// round 5
// speedup vs baseline: 1.2130x; 1.2130x over previous
#include <cuda_runtime.h>
#include <cuda_bf16.h>

// Problem constants
#define B_    16
#define C_    64
#define H_    256
#define W_    256
#define HW_   (H_ * W_)            // 65536
#define HW4_  (HW_ / 4)            // 16384
#define BHW_  (B_ * HW_)           // 1048576
#define K_    11
#define P_    5
#define EPS_  1e-6f

#define CSEG_ 4                    // channel split factor
#define CPT_  (C_ / CSEG_)         // 16 channels per segment

// Scratch: 3 maps (sxx, sxy, syy) before and after horizontal blur. 12 MiB each.
__device__ float d_S[3 * BHW_];
__device__ float d_T[3 * BHW_];

// ---------------------------------------------------------------------------
// Kernel 0: zero d_S (accumulation target for the split reduction).
// ---------------------------------------------------------------------------
__global__ void k_zero() {
    int i = blockIdx.x * blockDim.x + threadIdx.x;   // 0 .. 3*BHW/4-1
    reinterpret_cast<float4*>(d_S)[i] = make_float4(0.f, 0.f, 0.f, 0.f);
}

// ---------------------------------------------------------------------------
// Kernel 1: channel reduction, 4-way split over C.
// grid = 4096 blocks x 256 thr. Block segment = blockIdx >> 10 (contiguous, so
// each scheduling wave mostly covers one segment -> low atomic collision).
// Each thread: one float4 position-tile over 16 channels, loads batched 4 deep
// (8 float4 LDGs in flight) for MLP; streaming cache hints (no reuse).
// Results accumulated into d_S via RED.f32 (L2-resident, ~no extra DRAM).
// ---------------------------------------------------------------------------
__global__ void k_reduce(const float4* __restrict__ x, const float4* __restrict__ y) {
    int idx = blockIdx.x * blockDim.x + threadIdx.x;   // 0 .. 4*262144-1
    int seg = idx >> 18;                               // channel quarter
    int pos = idx & (B_ * HW4_ - 1);                   // float4 position 0..262143
    int b   = pos >> 14;
    int p   = pos & (HW4_ - 1);

    const float4* xp = x + (size_t)b * (C_ * HW4_) + (size_t)(seg * CPT_) * HW4_ + p;
    const float4* yp = y + (size_t)b * (C_ * HW4_) + (size_t)(seg * CPT_) * HW4_ + p;

    float4 axx = make_float4(0.f, 0.f, 0.f, 0.f);
    float4 axy = make_float4(0.f, 0.f, 0.f, 0.f);
    float4 ayy = make_float4(0.f, 0.f, 0.f, 0.f);

#pragma unroll
    for (int c = 0; c < CPT_; c += 4) {
        float4 xv0 = __ldcs(xp + (c + 0) * HW4_);
        float4 xv1 = __ldcs(xp + (c + 1) * HW4_);
        float4 xv2 = __ldcs(xp + (c + 2) * HW4_);
        float4 xv3 = __ldcs(xp + (c + 3) * HW4_);
        float4 yv0 = __ldcs(yp + (c + 0) * HW4_);
        float4 yv1 = __ldcs(yp + (c + 1) * HW4_);
        float4 yv2 = __ldcs(yp + (c + 2) * HW4_);
        float4 yv3 = __ldcs(yp + (c + 3) * HW4_);

        axx.x += xv0.x*xv0.x; axx.y += xv0.y*xv0.y; axx.z += xv0.z*xv0.z; axx.w += xv0.w*xv0.w;
        axy.x += xv0.x*yv0.x; axy.y += xv0.y*yv0.y; axy.z += xv0.z*yv0.z; axy.w += xv0.w*yv0.w;
        ayy.x += yv0.x*yv0.x; ayy.y += yv0.y*yv0.y; ayy.z += yv0.z*yv0.z; ayy.w += yv0.w*yv0.w;

        axx.x += xv1.x*xv1.x; axx.y += xv1.y*xv1.y; axx.z += xv1.z*xv1.z; axx.w += xv1.w*xv1.w;
        axy.x += xv1.x*yv1.x; axy.y += xv1.y*yv1.y; axy.z += xv1.z*yv1.z; axy.w += xv1.w*yv1.w;
        ayy.x += yv1.x*yv1.x; ayy.y += yv1.y*yv1.y; ayy.z += yv1.z*yv1.z; ayy.w += yv1.w*yv1.w;

        axx.x += xv2.x*xv2.x; axx.y += xv2.y*xv2.y; axx.z += xv2.z*xv2.z; axx.w += xv2.w*xv2.w;
        axy.x += xv2.x*yv2.x; axy.y += xv2.y*yv2.y; axy.z += xv2.z*yv2.z; axy.w += xv2.w*yv2.w;
        ayy.x += yv2.x*yv2.x; ayy.y += yv2.y*yv2.y; ayy.z += yv2.z*yv2.z; ayy.w += yv2.w*yv2.w;

        axx.x += xv3.x*xv3.x; axx.y += xv3.y*xv3.y; axx.z += xv3.z*xv3.z; axx.w += xv3.w*xv3.w;
        axy.x += xv3.x*yv3.x; axy.y += xv3.y*yv3.y; axy.z += xv3.z*yv3.z; axy.w += xv3.w*yv3.w;
        ayy.x += yv3.x*yv3.x; ayy.y += yv3.y*yv3.y; ayy.z += yv3.z*yv3.z; ayy.w += yv3.w*yv3.w;
    }

    int o = pos * 4;   // scalar base index within a map
    atomicAdd(&d_S[o + 0], axx.x); atomicAdd(&d_S[o + 1], axx.y);
    atomicAdd(&d_S[o + 2], axx.z); atomicAdd(&d_S[o + 3], axx.w);
    atomicAdd(&d_S[BHW_ + o + 0], axy.x); atomicAdd(&d_S[BHW_ + o + 1], axy.y);
    atomicAdd(&d_S[BHW_ + o + 2], axy.z); atomicAdd(&d_S[BHW_ + o + 3], axy.w);
    atomicAdd(&d_S[2*BHW_ + o + 0], ayy.x); atomicAdd(&d_S[2*BHW_ + o + 1], ayy.y);
    atomicAdd(&d_S[2*BHW_ + o + 2], ayy.z); atomicAdd(&d_S[2*BHW_ + o + 3], ayy.w);
}

// ---------------------------------------------------------------------------
// Kernel 2: horizontal 11-tap blur, float4-vectorized. One thread -> 4 outputs.
// Taps for outputs [4w..4w+3] span floats [4w-5 .. 4w+8] which live entirely in
// float4 blocks [w-2 .. w+2] (rows are float4-aligned), so whole-float4 zero
// masking at row edges is exact. 5 loads + 44 FMA per thread.
// g1[i] = gauss[5][i] * rsqrt(gauss[5][5]) recovers the exact 1D factor.
// ---------------------------------------------------------------------------
__global__ void k_hblur(const float* __restrict__ gauss) {
    __shared__ float g1[K_];
    if (threadIdx.x < K_)
        g1[threadIdx.x] = gauss[5 * K_ + threadIdx.x] * rsqrtf(gauss[5 * K_ + 5]);
    __syncthreads();

    int idx4 = blockIdx.x * blockDim.x + threadIdx.x;   // 0 .. 3*BHW/4-1
    int w4       = idx4 & (W_ / 4 - 1);                 // 0..63
    int rowbase4 = idx4 - w4;

    const float4* S4 = reinterpret_cast<const float4*>(d_S);

    float s[20];
#pragma unroll
    for (int j = 0; j < 5; j++) {
        int ww = w4 + j - 2;
        float4 v = make_float4(0.f, 0.f, 0.f, 0.f);
        if ((unsigned)ww < (unsigned)(W_ / 4))
            v = S4[rowbase4 + ww];
        s[4*j+0] = v.x; s[4*j+1] = v.y; s[4*j+2] = v.z; s[4*j+3] = v.w;
    }

    float4 acc = make_float4(0.f, 0.f, 0.f, 0.f);
#pragma unroll
    for (int k = 0; k < K_; k++) {
        float g = g1[k];
        acc.x += g * s[k + 3];
        acc.y += g * s[k + 4];
        acc.z += g * s[k + 5];
        acc.w += g * s[k + 6];
    }
    reinterpret_cast<float4*>(d_T)[idx4] = acc;
}

// ---------------------------------------------------------------------------
// Kernel 3: vertical 11-tap blur (all 3 maps) + cosine combine, float4 output.
// 33 float4 loads (L2-resident), 132 FMA, 4 combines per thread.
// ---------------------------------------------------------------------------
__global__ void k_vblur(const float* __restrict__ gauss, float4* __restrict__ out) {
    __shared__ float g1[K_];
    if (threadIdx.x < K_)
        g1[threadIdx.x] = gauss[5 * K_ + threadIdx.x] * rsqrtf(gauss[5 * K_ + 5]);
    __syncthreads();

    int idx4 = blockIdx.x * blockDim.x + threadIdx.x;   // 0 .. BHW/4-1
    int w4 = idx4 & (W_ / 4 - 1);
    int h  = (idx4 >> 6) & (H_ - 1);
    int b  = idx4 >> 14;

    const float4* T4 = reinterpret_cast<const float4*>(d_T);
    int base = b * HW4_ + w4;

    float4 sxx = make_float4(0.f, 0.f, 0.f, 0.f);
    float4 sxy = make_float4(0.f, 0.f, 0.f, 0.f);
    float4 syy = make_float4(0.f, 0.f, 0.f, 0.f);

#pragma unroll
    for (int k = 0; k < K_; k++) {
        int hh = h + k - P_;
        if ((unsigned)hh < (unsigned)H_) {
            float g  = g1[k];
            int  off = base + hh * (W_ / 4);
            float4 a = T4[off];
            float4 c = T4[off + BHW_ / 4];
            float4 d = T4[off + 2 * (BHW_ / 4)];
            sxx.x += g*a.x; sxx.y += g*a.y; sxx.z += g*a.z; sxx.w += g*a.w;
            sxy.x += g*c.x; sxy.y += g*c.y; sxy.z += g*c.z; sxy.w += g*c.w;
            syy.x += g*d.x; syy.y += g*d.y; syy.z += g*d.z; syy.w += g*d.w;
        }
    }

    float4 r;
    r.x = sxy.x / (sqrtf(sxx.x) * sqrtf(syy.x) + EPS_);
    r.y = sxy.y / (sqrtf(sxx.y) * sqrtf(syy.y) + EPS_);
    r.z = sxy.z / (sqrtf(sxx.z) * sqrtf(syy.z) + EPS_);
    r.w = sxy.w / (sqrtf(sxx.w) * sqrtf(syy.w) + EPS_);
    out[idx4] = r;
}

// ---------------------------------------------------------------------------
extern "C" void kernel_launch(void* const* d_in, const int* in_sizes, int n_in,
                              void* d_out, int out_size) {
    const float4* x     = (const float4*)d_in[0];
    const float4* y     = (const float4*)d_in[1];
    const float*  gauss = (const float*)d_in[2];
    float4*       out   = (float4*)d_out;

    k_zero  <<<3 * BHW_ / 4 / 256, 256>>>();
    k_reduce<<<CSEG_ * B_ * HW4_ / 256, 256>>>(x, y);          // 4096 blocks
    k_hblur <<<3 * BHW_ / 4 / 256, 256>>>(gauss);              // 3072 blocks
    k_vblur <<<BHW_ / 4 / 256, 256>>>(gauss, out);             // 1024 blocks
}